// round 15
// baseline (speedup 1.0000x reference)
#include <cuda_runtime.h>
#include <cuda_fp16.h>

typedef unsigned int u32;
typedef unsigned long long u64;

#define HIDN 256
#define EDIM 64
#define MAXN 50000
#define MAXE 800000
#define EM   128           // rows per CTA (edge/node/pnode)
#define ETH  512
#define EETH 256           // edge threads (8 warps, 2x4 grid of 64x64 tiles)
#define NCW1 32
#define NCEA 4
#define NC2  16
#define NS2  8
#define NCN1 32
#define NCN2 16

// edge smem (bytes)
#define SE_BIAS 0          // 5*256 f32 = 5120
#define SE_S    5120       // 128 int
#define SE_D    5632
#define SE_REL  6144       // 128*3 f32
#define SE_DIST 7680
#define SE_CW   8192
#define SE_A    8704       // 2 bufs * 2 ch * 1536 u32 = 24576
#define SE_B    33280      // 2 bufs * 2 ch * 3072 u32 (hi) = 49152
#define SE_M    82432      // 128*132 u32 = 67584
#define SMEM_EDGE 150016

// P / node kernel smem — R13 layout
#define SOP_A 0            // 24576
#define SOP_B 24576        // 98304
#define SMEM_P 122880
#define SON_M 122880       // 67584
#define SON_BIAS 190464    // 2048
#define SMEM_NODE 192512

// ---------------- device globals ---------------------------------------------
__device__ u32 g_We1p[NCW1 * 4096];
__device__ u32 g_Weap[NCEA * 4096];
__device__ u32 g_We2p[NC2 * 4096];
__device__ u32 g_Wc1p[NC2 * 4096];
__device__ u32 g_Wn1p[NCN1 * 4096];
__device__ u32 g_Wn2p[NCN2 * 4096];
__device__ u32 g_hf[(size_t)MAXN * 128];
__device__ u32 g_ea16[(size_t)MAXE * 32];
__device__ u32 g_Ph1[(size_t)MAXN * 128];
__device__ u32 g_Ph2[(size_t)MAXN * 128];
__device__ u32 g_mif[(size_t)MAXN * 128];
__device__ float g_mi[(size_t)MAXN * HIDN];

// ---------------- helpers -----------------------------------------------------
__device__ __forceinline__ float silu_f(float v) {
    return v * (1.0f / (1.0f + __expf(-v)));
}
__device__ __forceinline__ u32 packh2(float a, float b) {
    __half2 h = __floats2half2_rn(a, b);
    return *(u32*)&h;
}
__device__ __forceinline__ u32 hadd2u(u32 a, u32 b) {
    __half2 r = __hadd2(*(__half2*)&a, *(__half2*)&b);
    return *(u32*)&r;
}
__device__ __forceinline__ void hsplit(float v, u32& hi, u32& lo) {
    __half h = __float2half_rn(v);
    __half l = __float2half_rn(v - __half2float(h));
    hi = (u32)__half_as_ushort(h);
    lo = (u32)__half_as_ushort(l);
}
__device__ __forceinline__ void mma_f16(float c[4], const u32 a[4], u32 b0, u32 b1) {
    asm volatile(
        "mma.sync.aligned.m16n8k16.row.col.f32.f16.f16.f32 "
        "{%0,%1,%2,%3}, {%4,%5,%6,%7}, {%8,%9}, {%0,%1,%2,%3};"
        : "+f"(c[0]), "+f"(c[1]), "+f"(c[2]), "+f"(c[3])
        : "r"(a[0]), "r"(a[1]), "r"(a[2]), "r"(a[3]), "r"(b0), "r"(b1));
}
__device__ __forceinline__ void ldsm4(u32 r[4], u32 addr) {
    asm volatile("ldmatrix.sync.aligned.m8n8.x4.shared.b16 {%0,%1,%2,%3}, [%4];"
                 : "=r"(r[0]), "=r"(r[1]), "=r"(r[2]), "=r"(r[3]) : "r"(addr));
}
__device__ __forceinline__ u32 cvta_s(const void* p) {
    return (u32)__cvta_generic_to_shared(p);
}
__device__ __forceinline__ void red2(float* p, float a, float b) {
    asm volatile("red.global.add.v2.f32 [%0], {%1,%2};"
                 :: "l"(p), "f"(a), "f"(b) : "memory");
}

// 2-pass fp16 MMA over 32x64 tile (pnode only)
__device__ __forceinline__ void do_chunk(float (*acc)[4],
    const u32* __restrict__ A, int astride, const u32* __restrict__ B,
    int wm, int wn, int lane)
{
    const int sel = lane >> 3, lrow = lane & 7;
    u32 a0[4], a1[4];
    {
        u32 ab = cvta_s(A) + (((u32)(wm * 32 + (sel & 1) * 8 + lrow) * astride
                               + (u32)(sel >> 1) * 4) << 2);
        ldsm4(a0, ab);
        ldsm4(a1, ab + ((u32)astride << 6));
    }
    const u32 bb = cvta_s(B);
    #pragma unroll
    for (int ntp = 0; ntp < 4; ntp++) {
        u32 boff = (((u32)(wn * 64 + ntp * 16 + (sel >> 1) * 8 + lrow) * 12
                     + (u32)(sel & 1) * 4) << 2);
        u32 bh[4], bl[4];
        ldsm4(bh, bb + boff);
        ldsm4(bl, bb + 12288 + boff);
        #pragma unroll
        for (int sub = 0; sub < 2; sub++) {
            int nt = 2 * ntp + sub;
            mma_f16(acc[nt],     a0, bh[2*sub], bh[2*sub+1]);
            mma_f16(acc[nt],     a0, bl[2*sub], bl[2*sub+1]);
            mma_f16(acc[8 + nt], a1, bh[2*sub], bh[2*sub+1]);
            mma_f16(acc[8 + nt], a1, bl[2*sub], bl[2*sub+1]);
        }
    }
}

// 1-pass (hi-only) fp16 MMA over 32x64 tile (node kernel)
__device__ __forceinline__ void do_chunk_hi(float (*acc)[4],
    const u32* __restrict__ A, int astride, const u32* __restrict__ B,
    int wm, int wn, int lane)
{
    const int sel = lane >> 3, lrow = lane & 7;
    u32 a0[4], a1[4];
    {
        u32 ab = cvta_s(A) + (((u32)(wm * 32 + (sel & 1) * 8 + lrow) * astride
                               + (u32)(sel >> 1) * 4) << 2);
        ldsm4(a0, ab);
        ldsm4(a1, ab + ((u32)astride << 6));
    }
    const u32 bb = cvta_s(B);
    #pragma unroll
    for (int ntp = 0; ntp < 4; ntp++) {
        u32 boff = (((u32)(wn * 64 + ntp * 16 + (sel >> 1) * 8 + lrow) * 12
                     + (u32)(sel & 1) * 4) << 2);
        u32 bh[4];
        ldsm4(bh, bb + boff);
        #pragma unroll
        for (int sub = 0; sub < 2; sub++) {
            int nt = 2 * ntp + sub;
            mma_f16(acc[nt],     a0, bh[2*sub], bh[2*sub+1]);
            mma_f16(acc[8 + nt], a1, bh[2*sub], bh[2*sub+1]);
        }
    }
}

// 1-pass hi-only fp16 MMA over a 64x64 warp tile (edge kernel)
__device__ __forceinline__ void do_chunk_hi64(float (*acc)[4],
    const u32* __restrict__ A, int astride, const u32* __restrict__ B,
    int wm, int wn, int lane)
{
    const int sel = lane >> 3, lrow = lane & 7;
    u32 a[4][4];
    {
        u32 ab = cvta_s(A) + (((u32)(wm * 64 + (sel & 1) * 8 + lrow) * astride
                               + (u32)(sel >> 1) * 4) << 2);
        const u32 step = (u32)astride << 6;   // 16 rows
        ldsm4(a[0], ab);
        ldsm4(a[1], ab + step);
        ldsm4(a[2], ab + 2 * step);
        ldsm4(a[3], ab + 3 * step);
    }
    const u32 bb = cvta_s(B);
    #pragma unroll
    for (int ntp = 0; ntp < 4; ntp++) {
        u32 boff = (((u32)(wn * 64 + ntp * 16 + (sel >> 1) * 8 + lrow) * 12
                     + (u32)(sel & 1) * 4) << 2);
        u32 bh[4];
        ldsm4(bh, bb + boff);
        #pragma unroll
        for (int sub = 0; sub < 2; sub++) {
            int nt = 2 * ntp + sub;
            #pragma unroll
            for (int mt = 0; mt < 4; mt++)
                mma_f16(acc[mt * 8 + nt], a[mt], bh[2*sub], bh[2*sub+1]);
        }
    }
}

// ---------------- prep kernels -------------------------------------------------
__global__ void prep_weights(const float* __restrict__ We1,
                             const float* __restrict__ We2,
                             const float* __restrict__ Wc1,
                             const float* __restrict__ Wn1,
                             const float* __restrict__ Wn2)
{
    int i = blockIdx.x * blockDim.x + threadIdx.x;
    const int B1 = NCW1 * 2048;
    const int B2 = B1 + NC2 * 2048;
    const int B3 = B2 + NC2 * 2048;
    const int B4 = B3 + NCEA * 2048;
    const int B5 = B4 + NCN1 * 2048;
    const int B6 = B5 + NCN2 * 2048;
    const float* W; u32* dst; int j, kbase = 0, Kmax;
    if (i < B1)      { W = We1; dst = g_We1p; j = i;      Kmax = 577; }
    else if (i < B2) { W = We2; dst = g_We2p; j = i - B1; Kmax = 256; }
    else if (i < B3) { W = Wc1; dst = g_Wc1p; j = i - B2; Kmax = 256; }
    else if (i < B4) { W = We1; dst = g_Weap; j = i - B3; kbase = 513; Kmax = 577; }
    else if (i < B5) { W = Wn1; dst = g_Wn1p; j = i - B4; Kmax = 512; }
    else if (i < B6) { W = Wn2; dst = g_Wn2p; j = i - B5; Kmax = 256; }
    else return;
    int c = j / 2048, r = j % 2048;
    int n = r >> 3, kp = r & 7;
    int k = kbase + 16 * c + 2 * kp;
    float v0 = (k     < Kmax) ? W[(size_t)k * 256 + n]       : 0.f;
    float v1 = (k + 1 < Kmax) ? W[(size_t)(k + 1) * 256 + n] : 0.f;
    u32 h0, l0, h1, l1;
    hsplit(v0, h0, l0);
    hsplit(v1, h1, l1);
    dst[c * 4096 + n * 8 + kp]        = h0 | (h1 << 16);
    dst[c * 4096 + 2048 + n * 8 + kp] = l0 | (l1 << 16);
}

// fused: prep_h + prep_ea + mi-zero + xout-seed, grid-strided
__global__ void prep_data(const float* __restrict__ h,
                          const float* __restrict__ ea,
                          const float* __restrict__ x,
                          float* __restrict__ mi,
                          float* __restrict__ xout,
                          int N, int E)
{
    const int nh  = N * 128;
    const int nea = E * 32;
    const int nmi = N * 128;
    const int nx  = N * 3;
    const int total = nh + nea + nmi + nx;
    for (int i = blockIdx.x * blockDim.x + threadIdx.x; i < total;
         i += gridDim.x * blockDim.x) {
        if (i < nh) {
            const float2 v = *(const float2*)&h[2 * (size_t)i];
            g_hf[i] = packh2(v.x, v.y);
        } else if (i < nh + nea) {
            int j = i - nh;
            const float2 v = *(const float2*)&ea[2 * (size_t)j];
            g_ea16[j] = packh2(v.x, v.y);
        } else if (i < nh + nea + nmi) {
            int j = i - nh - nea;
            *(float2*)&mi[2 * (size_t)j] = make_float2(0.f, 0.f);
        } else {
            int j = i - nh - nea - nmi;
            xout[j] = x[j];
        }
    }
}

__global__ void prep_mi(const float* __restrict__ mi, int N)
{
    int i = blockIdx.x * blockDim.x + threadIdx.x;
    if (i >= N * 128) return;
    const float2 v = *(const float2*)&mi[2 * (size_t)i];
    g_mif[i] = packh2(v.x, v.y);
}

// ---------------- P kernel (2-pass, 2-chunk stages) -----------------------------
__global__ void __launch_bounds__(ETH, 1)
pnode_mma(int N)
{
    extern __shared__ char smem[];
    u32* sA = (u32*)(smem + SOP_A);
    u32* sB = (u32*)(smem + SOP_B);

    const int tid  = threadIdx.x;
    const int lane = tid & 31, wid = tid >> 5;
    const int wm = wid >> 2, wn = wid & 3;
    const int g = lane >> 2, tig = lane & 3;
    const int n0 = blockIdx.x * EM;
    const int half = blockIdx.y;
    const u32* gW = g_We1p + (size_t)half * 16 * 4096;
    u32* out = half ? g_Ph2 : g_Ph1;

    float acc[16][4];
    #pragma unroll
    for (int q = 0; q < 16; q++) {
        acc[q][0] = 0.f; acc[q][1] = 0.f; acc[q][2] = 0.f; acc[q][3] = 0.f;
    }
    uint4 ra, rb[4];

    auto ldA = [&](int s) {
        int ch = tid >> 8, r = tid & 255;
        int row = r >> 1, q = r & 1;
        int node = min(n0 + row, N - 1);
        ra = *(const uint4*)&g_hf[(size_t)node * 128 + 8 * (2 * s + ch) + 4 * q];
    };
    auto stA = [&](int buf) {
        int ch = tid >> 8, r = tid & 255;
        int row = r >> 1, q = r & 1;
        *(uint4*)&sA[buf * 3072 + ch * 1536 + row * 12 + 4*q] = ra;
    };
    auto ldB = [&](int s) {
        int n = tid >> 1, q = tid & 1;
        int c0 = 2 * s, c1 = 2 * s + 1;
        rb[0] = *(const uint4*)&gW[c0 * 4096 + n * 8 + 4*q];
        rb[1] = *(const uint4*)&gW[c0 * 4096 + 2048 + n * 8 + 4*q];
        rb[2] = *(const uint4*)&gW[c1 * 4096 + n * 8 + 4*q];
        rb[3] = *(const uint4*)&gW[c1 * 4096 + 2048 + n * 8 + 4*q];
    };
    auto stB = [&](int buf) {
        int n = tid >> 1, q = tid & 1;
        u32 base = buf * 12288;
        *(uint4*)&sB[base + n * 12 + 4*q]               = rb[0];
        *(uint4*)&sB[base + 3072 + n * 12 + 4*q]        = rb[1];
        *(uint4*)&sB[base + 6144 + n * 12 + 4*q]        = rb[2];
        *(uint4*)&sB[base + 6144 + 3072 + n * 12 + 4*q] = rb[3];
    };

    ldA(0); ldB(0);
    stA(0); stB(0);
    __syncthreads();
    for (int s = 0; s < 8; s++) {
        if (s + 1 < 8) { ldA(s + 1); ldB(s + 1); }
        const u32* Ab = &sA[(s & 1) * 3072];
        const u32* Bb = &sB[(s & 1) * 12288];
        do_chunk(acc, Ab, 12, Bb, wm, wn, lane);
        do_chunk(acc, Ab + 1536, 12, Bb + 6144, wm, wn, lane);
        if (s + 1 < 8) { stA((s + 1) & 1); stB((s + 1) & 1); }
        __syncthreads();
    }
    #pragma unroll
    for (int mt = 0; mt < 2; mt++)
    #pragma unroll
    for (int nt = 0; nt < 8; nt++) {
        float* cc = acc[mt * 8 + nt];
        int c0 = wn * 64 + nt * 8 + 2 * tig;
        int r0 = wm * 32 + mt * 16 + g;
        if (n0 + r0 < N)
            out[(size_t)(n0 + r0) * 128 + (c0 >> 1)] = packh2(cc[0], cc[1]);
        if (n0 + r0 + 8 < N)
            out[(size_t)(n0 + r0 + 8) * 128 + (c0 >> 1)] = packh2(cc[2], cc[3]);
    }
}

// ---------------- edge kernel (128 edges, 256 threads, 64x64 warp tiles) --------
__global__ void __launch_bounds__(EETH, 1)
edge_mma(const float* __restrict__ x, const int* __restrict__ ei,
         const float* __restrict__ We1,
         const float* __restrict__ be1, const float* __restrict__ be2,
         const float* __restrict__ bc1, const float* __restrict__ Wc2,
         float* __restrict__ mi, float* __restrict__ xout, int E)
{
    extern __shared__ char smem[];
    float* sBias = (float*)(smem + SE_BIAS);
    int*   sS    = (int*)(smem + SE_S);
    int*   sD    = (int*)(smem + SE_D);
    float* srel  = (float*)(smem + SE_REL);
    float* sdist = (float*)(smem + SE_DIST);
    float* scw   = (float*)(smem + SE_CW);
    u32*   sA    = (u32*)(smem + SE_A);
    u32*   sB    = (u32*)(smem + SE_B);
    u32*   sM    = (u32*)(smem + SE_M);

    const int tid  = threadIdx.x;
    const int lane = tid & 31, wid = tid >> 5;    // 8 warps
    const int wm = wid >> 2, wn = wid & 3;        // 2 x 4 grid, 64x64 tiles
    const int g = lane >> 2, tig = lane & 3;
    const int e0 = blockIdx.x * EM;
    const int valid = min(EM, E - e0);

    {
        sBias[tid]        = __ldg(&be1[tid]);
        sBias[256 + tid]  = __ldg(&be2[tid]);
        sBias[512 + tid]  = __ldg(&bc1[tid]);
        sBias[768 + tid]  = __ldg(&Wc2[tid]);
        sBias[1024 + tid] = __ldg(&We1[512 * 256 + tid]);
    }
    if (tid < EM) {
        int er = min(e0 + tid, E - 1);
        int s = ei[er], d = ei[E + er];
        float rx = x[3*s]   - x[3*d];
        float ry = x[3*s+1] - x[3*d+1];
        float rz = x[3*s+2] - x[3*d+2];
        sS[tid] = s; sD[tid] = d;
        srel[3*tid] = rx; srel[3*tid+1] = ry; srel[3*tid+2] = rz;
        sdist[tid] = rx*rx + ry*ry + rz*rz;
        scw[tid] = 0.f;
    }
    __syncthreads();

    // P-landing: sM[r][:] = P1[src r] + P2[dst r]  (8 warps x 16 rows = 128)
    #pragma unroll
    for (int i = 0; i < 16; i++) {
        int r = wid * 16 + i;
        const uint4 pa = *(const uint4*)&g_Ph1[(size_t)sS[r] * 128 + (lane << 2)];
        const uint4 pb = *(const uint4*)&g_Ph2[(size_t)sD[r] * 128 + (lane << 2)];
        uint4 s;
        s.x = hadd2u(pa.x, pb.x); s.y = hadd2u(pa.y, pb.y);
        s.z = hadd2u(pa.z, pb.z); s.w = hadd2u(pa.w, pb.w);
        *(uint4*)&sM[r * 132 + (lane << 2)] = s;
    }

    float acc[32][4];
    uint4 ra[2], rb[4];

    // A staging (GEMM1, ea): 2 chunks/stage, 512 uint4 slots, 2 per thread
    auto ldA1 = [&](int s) {
        #pragma unroll
        for (int i = 0; i < 2; i++) {
            int slot = tid + 256 * i;
            int ch = slot >> 8, r = slot & 255;
            int row = r >> 1, q = r & 1;
            int er = min(e0 + row, E - 1);
            ra[i] = *(const uint4*)&g_ea16[(size_t)er * 32 + 8 * (2 * s + ch) + 4 * q];
        }
    };
    auto stA1 = [&](int buf) {
        #pragma unroll
        for (int i = 0; i < 2; i++) {
            int slot = tid + 256 * i;
            int ch = slot >> 8, r = slot & 255;
            int row = r >> 1, q = r & 1;
            *(uint4*)&sA[buf * 3072 + ch * 1536 + row * 12 + 4*q] = ra[i];
        }
    };
    // B staging (hi-only): 2 chunks/stage, 1024 uint4 slots, 4 per thread
    auto ldB_hi = [&](const u32* __restrict__ gW, int s) {
        #pragma unroll
        for (int i = 0; i < 4; i++) {
            int slot = tid + 256 * i;
            int ch = slot >> 9, r = slot & 511;
            int n = r >> 1, q = r & 1;
            rb[i] = *(const uint4*)&gW[(2 * s + ch) * 4096 + n * 8 + 4*q];
        }
    };
    auto stB_hi = [&](int buf) {
        #pragma unroll
        for (int i = 0; i < 4; i++) {
            int slot = tid + 256 * i;
            int ch = slot >> 9, r = slot & 511;
            int n = r >> 1, q = r & 1;
            *(uint4*)&sB[buf * 6144 + ch * 3072 + n * 12 + 4*q] = rb[i];
        }
    };
    auto zacc = [&]() {
        #pragma unroll
        for (int q = 0; q < 32; q++) {
            acc[q][0] = 0.f; acc[q][1] = 0.f; acc[q][2] = 0.f; acc[q][3] = 0.f;
        }
    };

    // ===== GEMM1: acc = ea @ Weap (K=64, hi-only, 2 stages) =====
    zacc();
    ldA1(0); ldB_hi(g_Weap, 0);
    stA1(0); stB_hi(0);
    __syncthreads();
    for (int s = 0; s < 2; s++) {
        if (s == 0) { ldA1(1); ldB_hi(g_Weap, 1); }
        const u32* Ab = &sA[(s & 1) * 3072];
        const u32* Bb = &sB[(s & 1) * 6144];
        do_chunk_hi64(acc, Ab, 12, Bb, wm, wn, lane);
        do_chunk_hi64(acc, Ab + 1536, 12, Bb + 3072, wm, wn, lane);
        if (s == 0) { stA1(1); stB_hi(1); }
        __syncthreads();
    }
    // epilogue 1: m1 = silu(acc + P + dist*W512 + be1) -> sM
    #pragma unroll
    for (int mt = 0; mt < 4; mt++)
    #pragma unroll
    for (int nt = 0; nt < 8; nt++) {
        float* cc = acc[mt * 8 + nt];
        int c0 = wn * 64 + nt * 8 + 2 * tig, kp = c0 >> 1;
        int r0 = wm * 64 + mt * 16 + g;
        float b0 = sBias[c0], b1 = sBias[c0 + 1];
        float w0 = sBias[1024 + c0], w1 = sBias[1024 + c0 + 1];
        #pragma unroll
        for (int hh = 0; hh < 2; hh++) {
            int r = r0 + 8 * hh;
            u32 pw = sM[r * 132 + kp];
            float2 p = __half22float2(*(__half2*)&pw);
            float ds = sdist[r];
            float v0 = silu_f(cc[2*hh]     + p.x + ds * w0 + b0);
            float v1 = silu_f(cc[2*hh + 1] + p.y + ds * w1 + b1);
            sM[r * 132 + kp] = packh2(v0, v1);
        }
    }
    __syncthreads();

    // ===== GEMM2: m1 @ We2 (hi-only, 8 stages x 2 chunks) =====
    zacc();
    ldB_hi(g_We2p, 0); stB_hi(0);
    __syncthreads();
    for (int s = 0; s < NS2; s++) {
        if (s + 1 < NS2) ldB_hi(g_We2p, s + 1);
        const u32* Bb = &sB[(s & 1) * 6144];
        do_chunk_hi64(acc, &sM[8 * (2 * s)],     132, Bb,        wm, wn, lane);
        do_chunk_hi64(acc, &sM[8 * (2 * s + 1)], 132, Bb + 3072, wm, wn, lane);
        if (s + 1 < NS2) stB_hi((s + 1) & 1);
        __syncthreads();
    }
    // epilogue 2: m_ij = silu(acc + be2) -> sM; scatter into g_mi[dst]
    #pragma unroll
    for (int mt = 0; mt < 4; mt++)
    #pragma unroll
    for (int nt = 0; nt < 8; nt++) {
        float* cc = acc[mt * 8 + nt];
        int c0 = wn * 64 + nt * 8 + 2 * tig, kp = c0 >> 1;
        int r0 = wm * 64 + mt * 16 + g;
        float b0 = sBias[256 + c0], b1 = sBias[256 + c0 + 1];
        float m00 = silu_f(cc[0] + b0), m01 = silu_f(cc[1] + b1);
        float m10 = silu_f(cc[2] + b0), m11 = silu_f(cc[3] + b1);
        sM[r0 * 132 + kp]       = packh2(m00, m01);
        sM[(r0 + 8) * 132 + kp] = packh2(m10, m11);
        if (r0 < valid)     red2(&mi[(size_t)sD[r0] * HIDN + c0], m00, m01);
        if (r0 + 8 < valid) red2(&mi[(size_t)sD[r0 + 8] * HIDN + c0], m10, m11);
    }
    __syncthreads();

    // ===== GEMM3: m_ij @ Wc1 (hi-only, 8 stages x 2 chunks) =====
    zacc();
    ldB_hi(g_Wc1p, 0); stB_hi(0);
    __syncthreads();
    for (int s = 0; s < NS2; s++) {
        if (s + 1 < NS2) ldB_hi(g_Wc1p, s + 1);
        const u32* Bb = &sB[(s & 1) * 6144];
        do_chunk_hi64(acc, &sM[8 * (2 * s)],     132, Bb,        wm, wn, lane);
        do_chunk_hi64(acc, &sM[8 * (2 * s + 1)], 132, Bb + 3072, wm, wn, lane);
        if (s + 1 < NS2) stB_hi((s + 1) & 1);
        __syncthreads();
    }
    // epilogue 3: coord_w scatter
    {
        float rs[4][2];
        #pragma unroll
        for (int mt = 0; mt < 4; mt++) { rs[mt][0] = 0.f; rs[mt][1] = 0.f; }
        #pragma unroll
        for (int mt = 0; mt < 4; mt++)
        #pragma unroll
        for (int nt = 0; nt < 8; nt++) {
            float* cc = acc[mt * 8 + nt];
            int c0 = wn * 64 + nt * 8 + 2 * tig;
            float b0 = sBias[512 + c0], b1 = sBias[512 + c0 + 1];
            float w0 = sBias[768 + c0], w1 = sBias[768 + c0 + 1];
            rs[mt][0] += silu_f(cc[0] + b0) * w0 + silu_f(cc[1] + b1) * w1;
            rs[mt][1] += silu_f(cc[2] + b0) * w0 + silu_f(cc[3] + b1) * w1;
        }
        #pragma unroll
        for (int mt = 0; mt < 4; mt++)
        #pragma unroll
        for (int hh = 0; hh < 2; hh++) {
            float v = rs[mt][hh];
            v += __shfl_xor_sync(0xffffffffu, v, 1);
            v += __shfl_xor_sync(0xffffffffu, v, 2);
            if (tig == 0)
                atomicAdd(&scw[wm * 64 + mt * 16 + g + 8 * hh], v);
        }
    }
    __syncthreads();
    if (tid < EM && tid < valid) {
        int dn = sD[tid];
        float cw = scw[tid];
        atomicAdd(&xout[(size_t)dn * 3 + 0], srel[3*tid + 0] * cw);
        atomicAdd(&xout[(size_t)dn * 3 + 1], srel[3*tid + 1] * cw);
        atomicAdd(&xout[(size_t)dn * 3 + 2], srel[3*tid + 2] * cw);
    }
}

// ---------------- node kernel (hi-only, 2-chunk stages, R13) ---------------------
__global__ void __launch_bounds__(ETH, 1)
node_mma(const float* __restrict__ h,
         const float* __restrict__ bn1, const float* __restrict__ bn2,
         float* __restrict__ hout, int N)
{
    extern __shared__ char smem[];
    u32*   sA    = (u32*)(smem + SOP_A);
    u32*   sB    = (u32*)(smem + SOP_B);
    u32*   sM    = (u32*)(smem + SON_M);
    float* sBias = (float*)(smem + SON_BIAS);

    const int tid  = threadIdx.x;
    const int lane = tid & 31, wid = tid >> 5;
    const int wm = wid >> 2, wn = wid & 3;
    const int g = lane >> 2, tig = lane & 3;
    const int n0 = blockIdx.x * EM;

    if (tid < 256) {
        sBias[tid]       = __ldg(&bn1[tid]);
        sBias[256 + tid] = __ldg(&bn2[tid]);
    }

    float acc[16][4];
    uint4 ra, rb[4];

    auto ldA = [&](int s) {
        int ch = tid >> 8, r = tid & 255;
        int row = r >> 1, q = r & 1;
        int c = 2 * s + ch;
        int node = min(n0 + row, N - 1);
        const u32* src = (c < 16)
            ? &g_hf [(size_t)node * 128 + 8 * c + 4 * q]
            : &g_mif[(size_t)node * 128 + 8 * (c - 16) + 4 * q];
        ra = *(const uint4*)src;
    };
    auto stA = [&](int buf) {
        int ch = tid >> 8, r = tid & 255;
        int row = r >> 1, q = r & 1;
        *(uint4*)&sA[buf * 3072 + ch * 1536 + row * 12 + 4*q] = ra;
    };
    auto ldB_hi = [&](const u32* __restrict__ gW, int s) {
        int n = tid >> 1, q = tid & 1;
        rb[0] = *(const uint4*)&gW[(2 * s) * 4096 + n * 8 + 4*q];
        rb[2] = *(const uint4*)&gW[(2 * s + 1) * 4096 + n * 8 + 4*q];
    };
    auto stB_hi = [&](int buf) {
        int n = tid >> 1, q = tid & 1;
        u32 base = buf * 12288;
        *(uint4*)&sB[base + n * 12 + 4*q]        = rb[0];
        *(uint4*)&sB[base + 6144 + n * 12 + 4*q] = rb[2];
    };
    auto zacc = [&]() {
        #pragma unroll
        for (int q = 0; q < 16; q++) {
            acc[q][0] = 0.f; acc[q][1] = 0.f; acc[q][2] = 0.f; acc[q][3] = 0.f;
        }
    };

    // ===== GEMM1: [h, m_i] @ Wn1 (K=512, 16 stages x 2 chunks, hi-only) =====
    zacc();
    ldA(0); ldB_hi(g_Wn1p, 0);
    stA(0); stB_hi(0);
    __syncthreads();
    for (int s = 0; s < 16; s++) {
        if (s + 1 < 16) { ldA(s + 1); ldB_hi(g_Wn1p, s + 1); }
        const u32* Ab = &sA[(s & 1) * 3072];
        const u32* Bb = &sB[(s & 1) * 12288];
        do_chunk_hi(acc, Ab, 12, Bb, wm, wn, lane);
        do_chunk_hi(acc, Ab + 1536, 12, Bb + 6144, wm, wn, lane);
        if (s + 1 < 16) { stA((s + 1) & 1); stB_hi((s + 1) & 1); }
        __syncthreads();
    }
    #pragma unroll
    for (int mt = 0; mt < 2; mt++)
    #pragma unroll
    for (int nt = 0; nt < 8; nt++) {
        float* cc = acc[mt * 8 + nt];
        int c0 = wn * 64 + nt * 8 + 2 * tig, kp = c0 >> 1;
        int r0 = wm * 32 + mt * 16 + g;
        float b0 = sBias[c0], b1 = sBias[c0 + 1];
        sM[r0 * 132 + kp]       = packh2(silu_f(cc[0] + b0), silu_f(cc[1] + b1));
        sM[(r0 + 8) * 132 + kp] = packh2(silu_f(cc[2] + b0), silu_f(cc[3] + b1));
    }
    __syncthreads();

    // ===== GEMM2: @ Wn2 (K=256, 8 stages x 2 chunks, hi-only) =====
    zacc();
    ldB_hi(g_Wn2p, 0); stB_hi(0);
    __syncthreads();
    for (int s = 0; s < 8; s++) {
        if (s + 1 < 8) ldB_hi(g_Wn2p, s + 1);
        const u32* Bb = &sB[(s & 1) * 12288];
        do_chunk_hi(acc, &sM[8 * (2 * s)],     132, Bb,        wm, wn, lane);
        do_chunk_hi(acc, &sM[8 * (2 * s + 1)], 132, Bb + 6144, wm, wn, lane);
        if (s + 1 < 8) stB_hi((s + 1) & 1);
        __syncthreads();
    }
    // epilogue: h_out = h + acc + bn2
    #pragma unroll
    for (int mt = 0; mt < 2; mt++)
    #pragma unroll
    for (int nt = 0; nt < 8; nt++) {
        float* cc = acc[mt * 8 + nt];
        int c0 = wn * 64 + nt * 8 + 2 * tig;
        int r0 = wm * 32 + mt * 16 + g;
        float b0 = sBias[256 + c0], b1 = sBias[256 + c0 + 1];
        #pragma unroll
        for (int hh = 0; hh < 2; hh++) {
            int node = n0 + r0 + 8 * hh;
            if (node < N) {
                float2 hv = *(const float2*)&h[(size_t)node * 256 + c0];
                *(float2*)&hout[(size_t)node * 256 + c0] =
                    make_float2(hv.x + cc[2*hh] + b0, hv.y + cc[2*hh + 1] + b1);
            }
        }
    }
}

// ---------------------------------------------------------------------------
extern "C" void kernel_launch(void* const* d_in, const int* in_sizes, int n_in,
                              void* d_out, int out_size)
{
    const float* h   = (const float*)d_in[0];
    const float* x   = (const float*)d_in[1];
    const int*   ei  = (const int*)  d_in[2];
    const float* ea  = (const float*)d_in[3];
    const float* We1 = (const float*)d_in[4];
    const float* be1 = (const float*)d_in[5];
    const float* We2 = (const float*)d_in[6];
    const float* be2 = (const float*)d_in[7];
    const float* Wn1 = (const float*)d_in[8];
    const float* bn1 = (const float*)d_in[9];
    const float* Wn2 = (const float*)d_in[10];
    const float* bn2 = (const float*)d_in[11];
    const float* Wc1 = (const float*)d_in[12];
    const float* bc1 = (const float*)d_in[13];
    const float* Wc2 = (const float*)d_in[14];

    const int N = in_sizes[0] / HIDN;
    const int E = in_sizes[2] / 2;

    float* hout = (float*)d_out;
    float* xout = hout + (size_t)N * HIDN;

    float* mi = nullptr;
    cudaGetSymbolAddress((void**)&mi, g_mi);

    cudaFuncSetAttribute(edge_mma,  cudaFuncAttributeMaxDynamicSharedMemorySize, SMEM_EDGE);
    cudaFuncSetAttribute(pnode_mma, cudaFuncAttributeMaxDynamicSharedMemorySize, SMEM_P);
    cudaFuncSetAttribute(node_mma,  cudaFuncAttributeMaxDynamicSharedMemorySize, SMEM_NODE);

    const int wItems = (NCW1 + 2 * NC2 + NCEA + NCN1 + NCN2) * 2048;
    prep_weights<<<(wItems + 255) / 256, 256>>>(We1, We2, Wc1, Wn1, Wn2);

    prep_data<<<4736, 256>>>(h, ea, x, mi, xout, N, E);

    dim3 pgrid((N + EM - 1) / EM, 2);
    pnode_mma<<<pgrid, ETH, SMEM_P>>>(N);

    edge_mma<<<(E + EM - 1) / EM, EETH, SMEM_EDGE>>>(x, ei, We1, be1, be2, bc1, Wc2,
                                                     mi, xout, E);
    prep_mi<<<(N * 128 + 255) / 256, 256>>>(mi, N);
    node_mma<<<(N + EM - 1) / EM, ETH, SMEM_NODE>>>(h, bn1, bn2, hout, N);
}

// round 16
// speedup vs baseline: 2.0999x; 2.0999x over previous
#include <cuda_runtime.h>
#include <cuda_fp16.h>

typedef unsigned int u32;
typedef unsigned long long u64;

#define HIDN 256
#define EDIM 64
#define MAXN 50000
#define MAXE 800000
#define EM   128
#define ETH  512
#define NCW1 32            // We1[0:512] chunks (P kernel)
#define NCEA 4             // We1[513:577] chunks (edge GEMM1)
#define NC2  16            // GEMM2/3: K=256
#define NS2  8
#define NCN1 32            // Wn1: K=512
#define NCN2 16            // Wn2: K=256

// edge smem (bytes) — R11/R13 layout
#define SO_BIAS 0          // 5*256 f32 = 5120
#define SO_S    5120
#define SO_D    5632
#define SO_REL  6144
#define SO_DIST 7680
#define SO_CW   8192
#define SO_A    8704       // 2 bufs * 2 ch * 1536 u32 = 24576
#define SO_B    33280      // 98304
#define SO_M    131584     // 128*132 u32 = 67584
#define SMEM_EDGE 199168

// P / node kernel smem
#define SOP_A 0            // 24576
#define SOP_B 24576        // 98304
#define SMEM_P 122880
#define SON_M 122880       // 67584
#define SON_BIAS 190464    // 2048
#define SMEM_NODE 192512

// ---------------- device globals ---------------------------------------------
__device__ u32 g_We1p[NCW1 * 4096];
__device__ u32 g_Weap[NCEA * 4096];
__device__ u32 g_We2p[NC2 * 4096];
__device__ u32 g_Wc1p[NC2 * 4096];
__device__ u32 g_Wn1p[NCN1 * 4096];
__device__ u32 g_Wn2p[NCN2 * 4096];
__device__ u32 g_hf[(size_t)MAXN * 128];
__device__ u32 g_ea16[(size_t)MAXE * 32];
__device__ u32 g_Ph1[(size_t)MAXN * 128];
__device__ u32 g_Ph2[(size_t)MAXN * 128];
__device__ u32 g_mif[(size_t)MAXN * 128];   // m_i as fp16 pairs
__device__ float g_mi[(size_t)MAXN * HIDN];

// ---------------- helpers -----------------------------------------------------
__device__ __forceinline__ float silu_f(float v) {
    return v * (1.0f / (1.0f + __expf(-v)));
}
__device__ __forceinline__ u32 packh2(float a, float b) {
    __half2 h = __floats2half2_rn(a, b);
    return *(u32*)&h;
}
__device__ __forceinline__ u32 hadd2u(u32 a, u32 b) {
    __half2 r = __hadd2(*(__half2*)&a, *(__half2*)&b);
    return *(u32*)&r;
}
__device__ __forceinline__ void hsplit(float v, u32& hi, u32& lo) {
    __half h = __float2half_rn(v);
    __half l = __float2half_rn(v - __half2float(h));
    hi = (u32)__half_as_ushort(h);
    lo = (u32)__half_as_ushort(l);
}
__device__ __forceinline__ void mma_f16(float c[4], const u32 a[4], u32 b0, u32 b1) {
    asm volatile(
        "mma.sync.aligned.m16n8k16.row.col.f32.f16.f16.f32 "
        "{%0,%1,%2,%3}, {%4,%5,%6,%7}, {%8,%9}, {%0,%1,%2,%3};"
        : "+f"(c[0]), "+f"(c[1]), "+f"(c[2]), "+f"(c[3])
        : "r"(a[0]), "r"(a[1]), "r"(a[2]), "r"(a[3]), "r"(b0), "r"(b1));
}
__device__ __forceinline__ void ldsm4(u32 r[4], u32 addr) {
    asm volatile("ldmatrix.sync.aligned.m8n8.x4.shared.b16 {%0,%1,%2,%3}, [%4];"
                 : "=r"(r[0]), "=r"(r[1]), "=r"(r[2]), "=r"(r[3]) : "r"(addr));
}
__device__ __forceinline__ u32 cvta_s(const void* p) {
    return (u32)__cvta_generic_to_shared(p);
}
__device__ __forceinline__ void red2(float* p, float a, float b) {
    asm volatile("red.global.add.v2.f32 [%0], {%1,%2};"
                 :: "l"(p), "f"(a), "f"(b) : "memory");
}

// 2-pass fp16 MMA (pnode only)
__device__ __forceinline__ void do_chunk(float (*acc)[4],
    const u32* __restrict__ A, int astride, const u32* __restrict__ B,
    int wm, int wn, int lane)
{
    const int sel = lane >> 3, lrow = lane & 7;
    u32 a0[4], a1[4];
    {
        u32 ab = cvta_s(A) + (((u32)(wm * 32 + (sel & 1) * 8 + lrow) * astride
                               + (u32)(sel >> 1) * 4) << 2);
        ldsm4(a0, ab);
        ldsm4(a1, ab + ((u32)astride << 6));
    }
    const u32 bb = cvta_s(B);
    #pragma unroll
    for (int ntp = 0; ntp < 4; ntp++) {
        u32 boff = (((u32)(wn * 64 + ntp * 16 + (sel >> 1) * 8 + lrow) * 12
                     + (u32)(sel & 1) * 4) << 2);
        u32 bh[4], bl[4];
        ldsm4(bh, bb + boff);
        ldsm4(bl, bb + 12288 + boff);
        #pragma unroll
        for (int sub = 0; sub < 2; sub++) {
            int nt = 2 * ntp + sub;
            mma_f16(acc[nt],     a0, bh[2*sub], bh[2*sub+1]);
            mma_f16(acc[nt],     a0, bl[2*sub], bl[2*sub+1]);
            mma_f16(acc[8 + nt], a1, bh[2*sub], bh[2*sub+1]);
            mma_f16(acc[8 + nt], a1, bl[2*sub], bl[2*sub+1]);
        }
    }
}

// 1-pass (hi-only) fp16 MMA — edge + node kernels
__device__ __forceinline__ void do_chunk_hi(float (*acc)[4],
    const u32* __restrict__ A, int astride, const u32* __restrict__ B,
    int wm, int wn, int lane)
{
    const int sel = lane >> 3, lrow = lane & 7;
    u32 a0[4], a1[4];
    {
        u32 ab = cvta_s(A) + (((u32)(wm * 32 + (sel & 1) * 8 + lrow) * astride
                               + (u32)(sel >> 1) * 4) << 2);
        ldsm4(a0, ab);
        ldsm4(a1, ab + ((u32)astride << 6));
    }
    const u32 bb = cvta_s(B);
    #pragma unroll
    for (int ntp = 0; ntp < 4; ntp++) {
        u32 boff = (((u32)(wn * 64 + ntp * 16 + (sel >> 1) * 8 + lrow) * 12
                     + (u32)(sel & 1) * 4) << 2);
        u32 bh[4];
        ldsm4(bh, bb + boff);
        #pragma unroll
        for (int sub = 0; sub < 2; sub++) {
            int nt = 2 * ntp + sub;
            mma_f16(acc[nt],     a0, bh[2*sub], bh[2*sub+1]);
            mma_f16(acc[8 + nt], a1, bh[2*sub], bh[2*sub+1]);
        }
    }
}

// ---------------- prep kernels -------------------------------------------------
__global__ void prep_weights(const float* __restrict__ We1,
                             const float* __restrict__ We2,
                             const float* __restrict__ Wc1,
                             const float* __restrict__ Wn1,
                             const float* __restrict__ Wn2)
{
    int i = blockIdx.x * blockDim.x + threadIdx.x;
    const int B1 = NCW1 * 2048;
    const int B2 = B1 + NC2 * 2048;
    const int B3 = B2 + NC2 * 2048;
    const int B4 = B3 + NCEA * 2048;
    const int B5 = B4 + NCN1 * 2048;
    const int B6 = B5 + NCN2 * 2048;
    const float* W; u32* dst; int j, kbase = 0, Kmax;
    if (i < B1)      { W = We1; dst = g_We1p; j = i;      Kmax = 577; }
    else if (i < B2) { W = We2; dst = g_We2p; j = i - B1; Kmax = 256; }
    else if (i < B3) { W = Wc1; dst = g_Wc1p; j = i - B2; Kmax = 256; }
    else if (i < B4) { W = We1; dst = g_Weap; j = i - B3; kbase = 513; Kmax = 577; }
    else if (i < B5) { W = Wn1; dst = g_Wn1p; j = i - B4; Kmax = 512; }
    else if (i < B6) { W = Wn2; dst = g_Wn2p; j = i - B5; Kmax = 256; }
    else return;
    int c = j / 2048, r = j % 2048;
    int n = r >> 3, kp = r & 7;
    int k = kbase + 16 * c + 2 * kp;
    float v0 = (k     < Kmax) ? W[(size_t)k * 256 + n]       : 0.f;
    float v1 = (k + 1 < Kmax) ? W[(size_t)(k + 1) * 256 + n] : 0.f;
    u32 h0, l0, h1, l1;
    hsplit(v0, h0, l0);
    hsplit(v1, h1, l1);
    dst[c * 4096 + n * 8 + kp]        = h0 | (h1 << 16);
    dst[c * 4096 + 2048 + n * 8 + kp] = l0 | (l1 << 16);
}

// fused: prep_h + prep_ea + mi-zero + xout-seed, grid-strided
__global__ void prep_data(const float* __restrict__ h,
                          const float* __restrict__ ea,
                          const float* __restrict__ x,
                          float* __restrict__ mi,
                          float* __restrict__ xout,
                          int N, int E)
{
    const int nh  = N * 128;
    const int nea = E * 32;
    const int nmi = N * 128;
    const int nx  = N * 3;
    const int total = nh + nea + nmi + nx;
    for (int i = blockIdx.x * blockDim.x + threadIdx.x; i < total;
         i += gridDim.x * blockDim.x) {
        if (i < nh) {
            const float2 v = *(const float2*)&h[2 * (size_t)i];
            g_hf[i] = packh2(v.x, v.y);
        } else if (i < nh + nea) {
            int j = i - nh;
            const float2 v = *(const float2*)&ea[2 * (size_t)j];
            g_ea16[j] = packh2(v.x, v.y);
        } else if (i < nh + nea + nmi) {
            int j = i - nh - nea;
            *(float2*)&mi[2 * (size_t)j] = make_float2(0.f, 0.f);
        } else {
            int j = i - nh - nea - nmi;
            xout[j] = x[j];
        }
    }
}

__global__ void prep_mi(const float* __restrict__ mi, int N)
{
    int i = blockIdx.x * blockDim.x + threadIdx.x;
    if (i >= N * 128) return;
    const float2 v = *(const float2*)&mi[2 * (size_t)i];
    g_mif[i] = packh2(v.x, v.y);
}

// ---------------- P kernel (2-pass, 2-chunk stages) -----------------------------
__global__ void __launch_bounds__(ETH, 1)
pnode_mma(int N)
{
    extern __shared__ char smem[];
    u32* sA = (u32*)(smem + SOP_A);
    u32* sB = (u32*)(smem + SOP_B);

    const int tid  = threadIdx.x;
    const int lane = tid & 31, wid = tid >> 5;
    const int wm = wid >> 2, wn = wid & 3;
    const int g = lane >> 2, tig = lane & 3;
    const int n0 = blockIdx.x * EM;
    const int half = blockIdx.y;
    const u32* gW = g_We1p + (size_t)half * 16 * 4096;
    u32* out = half ? g_Ph2 : g_Ph1;

    float acc[16][4];
    #pragma unroll
    for (int q = 0; q < 16; q++) {
        acc[q][0] = 0.f; acc[q][1] = 0.f; acc[q][2] = 0.f; acc[q][3] = 0.f;
    }
    uint4 ra, rb[4];

    auto ldA = [&](int s) {
        int ch = tid >> 8, r = tid & 255;
        int row = r >> 1, q = r & 1;
        int node = min(n0 + row, N - 1);
        ra = *(const uint4*)&g_hf[(size_t)node * 128 + 8 * (2 * s + ch) + 4 * q];
    };
    auto stA = [&](int buf) {
        int ch = tid >> 8, r = tid & 255;
        int row = r >> 1, q = r & 1;
        *(uint4*)&sA[buf * 3072 + ch * 1536 + row * 12 + 4*q] = ra;
    };
    auto ldB = [&](int s) {
        int n = tid >> 1, q = tid & 1;
        int c0 = 2 * s, c1 = 2 * s + 1;
        rb[0] = *(const uint4*)&gW[c0 * 4096 + n * 8 + 4*q];
        rb[1] = *(const uint4*)&gW[c0 * 4096 + 2048 + n * 8 + 4*q];
        rb[2] = *(const uint4*)&gW[c1 * 4096 + n * 8 + 4*q];
        rb[3] = *(const uint4*)&gW[c1 * 4096 + 2048 + n * 8 + 4*q];
    };
    auto stB = [&](int buf) {
        int n = tid >> 1, q = tid & 1;
        u32 base = buf * 12288;
        *(uint4*)&sB[base + n * 12 + 4*q]               = rb[0];
        *(uint4*)&sB[base + 3072 + n * 12 + 4*q]        = rb[1];
        *(uint4*)&sB[base + 6144 + n * 12 + 4*q]        = rb[2];
        *(uint4*)&sB[base + 6144 + 3072 + n * 12 + 4*q] = rb[3];
    };

    ldA(0); ldB(0);
    stA(0); stB(0);
    __syncthreads();
    for (int s = 0; s < 8; s++) {
        if (s + 1 < 8) { ldA(s + 1); ldB(s + 1); }
        const u32* Ab = &sA[(s & 1) * 3072];
        const u32* Bb = &sB[(s & 1) * 12288];
        do_chunk(acc, Ab, 12, Bb, wm, wn, lane);
        do_chunk(acc, Ab + 1536, 12, Bb + 6144, wm, wn, lane);
        if (s + 1 < 8) { stA((s + 1) & 1); stB((s + 1) & 1); }
        __syncthreads();
    }
    #pragma unroll
    for (int mt = 0; mt < 2; mt++)
    #pragma unroll
    for (int nt = 0; nt < 8; nt++) {
        float* cc = acc[mt * 8 + nt];
        int c0 = wn * 64 + nt * 8 + 2 * tig;
        int r0 = wm * 32 + mt * 16 + g;
        if (n0 + r0 < N)
            out[(size_t)(n0 + r0) * 128 + (c0 >> 1)] = packh2(cc[0], cc[1]);
        if (n0 + r0 + 8 < N)
            out[(size_t)(n0 + r0 + 8) * 128 + (c0 >> 1)] = packh2(cc[2], cc[3]);
    }
}

// ---------------- edge kernel (R13: 2-chunk stages, hi-only B) -------------------
__global__ void __launch_bounds__(ETH, 1)
edge_mma(const float* __restrict__ x, const int* __restrict__ ei,
         const float* __restrict__ We1,
         const float* __restrict__ be1, const float* __restrict__ be2,
         const float* __restrict__ bc1, const float* __restrict__ Wc2,
         float* __restrict__ mi, float* __restrict__ xout, int E)
{
    extern __shared__ char smem[];
    float* sBias = (float*)(smem + SO_BIAS);
    int*   sS    = (int*)(smem + SO_S);
    int*   sD    = (int*)(smem + SO_D);
    float* srel  = (float*)(smem + SO_REL);
    float* sdist = (float*)(smem + SO_DIST);
    float* scw   = (float*)(smem + SO_CW);
    u32*   sA    = (u32*)(smem + SO_A);
    u32*   sB    = (u32*)(smem + SO_B);
    u32*   sM    = (u32*)(smem + SO_M);

    const int tid  = threadIdx.x;
    const int lane = tid & 31, wid = tid >> 5;
    const int wm = wid >> 2, wn = wid & 3;
    const int g = lane >> 2, tig = lane & 3;
    const int e0 = blockIdx.x * EM;
    const int valid = min(EM, E - e0);

    if (tid < 256) {
        sBias[tid]        = __ldg(&be1[tid]);
        sBias[256 + tid]  = __ldg(&be2[tid]);
        sBias[512 + tid]  = __ldg(&bc1[tid]);
        sBias[768 + tid]  = __ldg(&Wc2[tid]);
        sBias[1024 + tid] = __ldg(&We1[512 * 256 + tid]);
    }
    if (tid < EM) {
        int er = min(e0 + tid, E - 1);
        int s = ei[er], d = ei[E + er];
        float rx = x[3*s]   - x[3*d];
        float ry = x[3*s+1] - x[3*d+1];
        float rz = x[3*s+2] - x[3*d+2];
        sS[tid] = s; sD[tid] = d;
        srel[3*tid] = rx; srel[3*tid+1] = ry; srel[3*tid+2] = rz;
        sdist[tid] = rx*rx + ry*ry + rz*rz;
        scw[tid] = 0.f;
    }
    __syncthreads();

    // P-landing: sM[r][:] = P1[src r] + P2[dst r] (fp16, warp-coalesced)
    #pragma unroll
    for (int i = 0; i < 8; i++) {
        int r = wid * 8 + i;
        const uint4 pa = *(const uint4*)&g_Ph1[(size_t)sS[r] * 128 + (lane << 2)];
        const uint4 pb = *(const uint4*)&g_Ph2[(size_t)sD[r] * 128 + (lane << 2)];
        uint4 s;
        s.x = hadd2u(pa.x, pb.x); s.y = hadd2u(pa.y, pb.y);
        s.z = hadd2u(pa.z, pb.z); s.w = hadd2u(pa.w, pb.w);
        *(uint4*)&sM[r * 132 + (lane << 2)] = s;
    }

    float acc[16][4];
    uint4 ra, rb[4];

    auto ldA1 = [&](int s) {
        int ch = tid >> 8, r = tid & 255;
        int row = r >> 1, q = r & 1;
        int er = min(e0 + row, E - 1);
        ra = *(const uint4*)&g_ea16[(size_t)er * 32 + 8 * (2 * s + ch) + 4 * q];
    };
    auto stA1 = [&](int buf) {
        int ch = tid >> 8, r = tid & 255;
        int row = r >> 1, q = r & 1;
        *(uint4*)&sA[buf * 3072 + ch * 1536 + row * 12 + 4*q] = ra;
    };
    auto ldB_hi = [&](const u32* __restrict__ gW, int s) {
        int n = tid >> 1, q = tid & 1;
        rb[0] = *(const uint4*)&gW[(2 * s) * 4096 + n * 8 + 4*q];
        rb[2] = *(const uint4*)&gW[(2 * s + 1) * 4096 + n * 8 + 4*q];
    };
    auto stB_hi = [&](int buf) {
        int n = tid >> 1, q = tid & 1;
        u32 base = buf * 12288;
        *(uint4*)&sB[base + n * 12 + 4*q]        = rb[0];
        *(uint4*)&sB[base + 6144 + n * 12 + 4*q] = rb[2];
    };
    auto zacc = [&]() {
        #pragma unroll
        for (int q = 0; q < 16; q++) {
            acc[q][0] = 0.f; acc[q][1] = 0.f; acc[q][2] = 0.f; acc[q][3] = 0.f;
        }
    };

    // ===== GEMM1: acc = ea @ Weap (K=64, hi-only) =====
    zacc();
    ldA1(0); ldB_hi(g_Weap, 0);
    stA1(0); stB_hi(0);
    __syncthreads();
    for (int s = 0; s < 2; s++) {
        if (s == 0) { ldA1(1); ldB_hi(g_Weap, 1); }
        const u32* Ab = &sA[(s & 1) * 3072];
        const u32* Bb = &sB[(s & 1) * 12288];
        do_chunk_hi(acc, Ab, 12, Bb, wm, wn, lane);
        do_chunk_hi(acc, Ab + 1536, 12, Bb + 6144, wm, wn, lane);
        if (s == 0) { stA1(1); stB_hi(1); }
        __syncthreads();
    }
    // epilogue 1: m1 = silu(acc + P + dist*W512 + be1) -> sM
    #pragma unroll
    for (int mt = 0; mt < 2; mt++)
    #pragma unroll
    for (int nt = 0; nt < 8; nt++) {
        float* cc = acc[mt * 8 + nt];
        int c0 = wn * 64 + nt * 8 + 2 * tig, kp = c0 >> 1;
        int r0 = wm * 32 + mt * 16 + g;
        float b0 = sBias[c0], b1 = sBias[c0 + 1];
        float w0 = sBias[1024 + c0], w1 = sBias[1024 + c0 + 1];
        #pragma unroll
        for (int hh = 0; hh < 2; hh++) {
            int r = r0 + 8 * hh;
            u32 pw = sM[r * 132 + kp];
            float2 p = __half22float2(*(__half2*)&pw);
            float ds = sdist[r];
            float v0 = silu_f(cc[2*hh]     + p.x + ds * w0 + b0);
            float v1 = silu_f(cc[2*hh + 1] + p.y + ds * w1 + b1);
            sM[r * 132 + kp] = packh2(v0, v1);
        }
    }
    __syncthreads();

    // ===== GEMM2: m1 @ We2 (hi-only, 8 stages x 2 chunks) =====
    zacc();
    ldB_hi(g_We2p, 0); stB_hi(0);
    __syncthreads();
    for (int s = 0; s < NS2; s++) {
        if (s + 1 < NS2) ldB_hi(g_We2p, s + 1);
        const u32* Bb = &sB[(s & 1) * 12288];
        do_chunk_hi(acc, &sM[8 * (2 * s)],     132, Bb,        wm, wn, lane);
        do_chunk_hi(acc, &sM[8 * (2 * s + 1)], 132, Bb + 6144, wm, wn, lane);
        if (s + 1 < NS2) stB_hi((s + 1) & 1);
        __syncthreads();
    }
    // epilogue 2: m_ij = silu(acc + be2) -> sM; scatter into g_mi[dst]
    #pragma unroll
    for (int mt = 0; mt < 2; mt++)
    #pragma unroll
    for (int nt = 0; nt < 8; nt++) {
        float* cc = acc[mt * 8 + nt];
        int c0 = wn * 64 + nt * 8 + 2 * tig, kp = c0 >> 1;
        int r0 = wm * 32 + mt * 16 + g;
        float b0 = sBias[256 + c0], b1 = sBias[256 + c0 + 1];
        float m00 = silu_f(cc[0] + b0), m01 = silu_f(cc[1] + b1);
        float m10 = silu_f(cc[2] + b0), m11 = silu_f(cc[3] + b1);
        sM[r0 * 132 + kp]       = packh2(m00, m01);
        sM[(r0 + 8) * 132 + kp] = packh2(m10, m11);
        if (r0 < valid)     red2(&mi[(size_t)sD[r0] * HIDN + c0], m00, m01);
        if (r0 + 8 < valid) red2(&mi[(size_t)sD[r0 + 8] * HIDN + c0], m10, m11);
    }
    __syncthreads();

    // ===== GEMM3: m_ij @ Wc1 (hi-only, 8 stages x 2 chunks) =====
    zacc();
    ldB_hi(g_Wc1p, 0); stB_hi(0);
    __syncthreads();
    for (int s = 0; s < NS2; s++) {
        if (s + 1 < NS2) ldB_hi(g_Wc1p, s + 1);
        const u32* Bb = &sB[(s & 1) * 12288];
        do_chunk_hi(acc, &sM[8 * (2 * s)],     132, Bb,        wm, wn, lane);
        do_chunk_hi(acc, &sM[8 * (2 * s + 1)], 132, Bb + 6144, wm, wn, lane);
        if (s + 1 < NS2) stB_hi((s + 1) & 1);
        __syncthreads();
    }
    // epilogue 3: coord_w scatter
    {
        float rs[2][2] = {{0.f, 0.f}, {0.f, 0.f}};
        #pragma unroll
        for (int mt = 0; mt < 2; mt++)
        #pragma unroll
        for (int nt = 0; nt < 8; nt++) {
            float* cc = acc[mt * 8 + nt];
            int c0 = wn * 64 + nt * 8 + 2 * tig;
            float b0 = sBias[512 + c0], b1 = sBias[512 + c0 + 1];
            float w0 = sBias[768 + c0], w1 = sBias[768 + c0 + 1];
            rs[mt][0] += silu_f(cc[0] + b0) * w0 + silu_f(cc[1] + b1) * w1;
            rs[mt][1] += silu_f(cc[2] + b0) * w0 + silu_f(cc[3] + b1) * w1;
        }
        #pragma unroll
        for (int mt = 0; mt < 2; mt++)
        #pragma unroll
        for (int hh = 0; hh < 2; hh++) {
            float v = rs[mt][hh];
            v += __shfl_xor_sync(0xffffffffu, v, 1);
            v += __shfl_xor_sync(0xffffffffu, v, 2);
            rs[mt][hh] = v;
        }
        if (tig == 0) {
            atomicAdd(&scw[wm * 32 + g],      rs[0][0]);
            atomicAdd(&scw[wm * 32 + 8 + g],  rs[0][1]);
            atomicAdd(&scw[wm * 32 + 16 + g], rs[1][0]);
            atomicAdd(&scw[wm * 32 + 24 + g], rs[1][1]);
        }
    }
    __syncthreads();
    if (tid < EM && tid < valid) {
        int dn = sD[tid];
        float cw = scw[tid];
        atomicAdd(&xout[(size_t)dn * 3 + 0], srel[3*tid + 0] * cw);
        atomicAdd(&xout[(size_t)dn * 3 + 1], srel[3*tid + 1] * cw);
        atomicAdd(&xout[(size_t)dn * 3 + 2], srel[3*tid + 2] * cw);
    }
}

// ---------------- node kernel (hi-only, 2-chunk stages) --------------------------
__global__ void __launch_bounds__(ETH, 1)
node_mma(const float* __restrict__ h,
         const float* __restrict__ bn1, const float* __restrict__ bn2,
         float* __restrict__ hout, int N)
{
    extern __shared__ char smem[];
    u32*   sA    = (u32*)(smem + SOP_A);
    u32*   sB    = (u32*)(smem + SOP_B);
    u32*   sM    = (u32*)(smem + SON_M);
    float* sBias = (float*)(smem + SON_BIAS);

    const int tid  = threadIdx.x;
    const int lane = tid & 31, wid = tid >> 5;
    const int wm = wid >> 2, wn = wid & 3;
    const int g = lane >> 2, tig = lane & 3;
    const int n0 = blockIdx.x * EM;

    if (tid < 256) {
        sBias[tid]       = __ldg(&bn1[tid]);
        sBias[256 + tid] = __ldg(&bn2[tid]);
    }

    float acc[16][4];
    uint4 ra, rb[4];

    auto ldA = [&](int s) {
        int ch = tid >> 8, r = tid & 255;
        int row = r >> 1, q = r & 1;
        int c = 2 * s + ch;
        int node = min(n0 + row, N - 1);
        const u32* src = (c < 16)
            ? &g_hf [(size_t)node * 128 + 8 * c + 4 * q]
            : &g_mif[(size_t)node * 128 + 8 * (c - 16) + 4 * q];
        ra = *(const uint4*)src;
    };
    auto stA = [&](int buf) {
        int ch = tid >> 8, r = tid & 255;
        int row = r >> 1, q = r & 1;
        *(uint4*)&sA[buf * 3072 + ch * 1536 + row * 12 + 4*q] = ra;
    };
    auto ldB_hi = [&](const u32* __restrict__ gW, int s) {
        int n = tid >> 1, q = tid & 1;
        rb[0] = *(const uint4*)&gW[(2 * s) * 4096 + n * 8 + 4*q];
        rb[2] = *(const uint4*)&gW[(2 * s + 1) * 4096 + n * 8 + 4*q];
    };
    auto stB_hi = [&](int buf) {
        int n = tid >> 1, q = tid & 1;
        u32 base = buf * 12288;
        *(uint4*)&sB[base + n * 12 + 4*q]        = rb[0];
        *(uint4*)&sB[base + 6144 + n * 12 + 4*q] = rb[2];
    };
    auto zacc = [&]() {
        #pragma unroll
        for (int q = 0; q < 16; q++) {
            acc[q][0] = 0.f; acc[q][1] = 0.f; acc[q][2] = 0.f; acc[q][3] = 0.f;
        }
    };

    // ===== GEMM1: [h, m_i] @ Wn1 (K=512, 16 stages x 2 chunks, hi-only) =====
    zacc();
    ldA(0); ldB_hi(g_Wn1p, 0);
    stA(0); stB_hi(0);
    __syncthreads();
    for (int s = 0; s < 16; s++) {
        if (s + 1 < 16) { ldA(s + 1); ldB_hi(g_Wn1p, s + 1); }
        const u32* Ab = &sA[(s & 1) * 3072];
        const u32* Bb = &sB[(s & 1) * 12288];
        do_chunk_hi(acc, Ab, 12, Bb, wm, wn, lane);
        do_chunk_hi(acc, Ab + 1536, 12, Bb + 6144, wm, wn, lane);
        if (s + 1 < 16) { stA((s + 1) & 1); stB_hi((s + 1) & 1); }
        __syncthreads();
    }
    #pragma unroll
    for (int mt = 0; mt < 2; mt++)
    #pragma unroll
    for (int nt = 0; nt < 8; nt++) {
        float* cc = acc[mt * 8 + nt];
        int c0 = wn * 64 + nt * 8 + 2 * tig, kp = c0 >> 1;
        int r0 = wm * 32 + mt * 16 + g;
        float b0 = sBias[c0], b1 = sBias[c0 + 1];
        sM[r0 * 132 + kp]       = packh2(silu_f(cc[0] + b0), silu_f(cc[1] + b1));
        sM[(r0 + 8) * 132 + kp] = packh2(silu_f(cc[2] + b0), silu_f(cc[3] + b1));
    }
    __syncthreads();

    // ===== GEMM2: @ Wn2 (K=256, 8 stages x 2 chunks, hi-only) =====
    zacc();
    ldB_hi(g_Wn2p, 0); stB_hi(0);
    __syncthreads();
    for (int s = 0; s < 8; s++) {
        if (s + 1 < 8) ldB_hi(g_Wn2p, s + 1);
        const u32* Bb = &sB[(s & 1) * 12288];
        do_chunk_hi(acc, &sM[8 * (2 * s)],     132, Bb,        wm, wn, lane);
        do_chunk_hi(acc, &sM[8 * (2 * s + 1)], 132, Bb + 6144, wm, wn, lane);
        if (s + 1 < 8) stB_hi((s + 1) & 1);
        __syncthreads();
    }
    // epilogue: h_out = h + acc + bn2
    #pragma unroll
    for (int mt = 0; mt < 2; mt++)
    #pragma unroll
    for (int nt = 0; nt < 8; nt++) {
        float* cc = acc[mt * 8 + nt];
        int c0 = wn * 64 + nt * 8 + 2 * tig;
        int r0 = wm * 32 + mt * 16 + g;
        float b0 = sBias[256 + c0], b1 = sBias[256 + c0 + 1];
        #pragma unroll
        for (int hh = 0; hh < 2; hh++) {
            int node = n0 + r0 + 8 * hh;
            if (node < N) {
                float2 hv = *(const float2*)&h[(size_t)node * 256 + c0];
                *(float2*)&hout[(size_t)node * 256 + c0] =
                    make_float2(hv.x + cc[2*hh] + b0, hv.y + cc[2*hh + 1] + b1);
            }
        }
    }
}

// ---------------------------------------------------------------------------
extern "C" void kernel_launch(void* const* d_in, const int* in_sizes, int n_in,
                              void* d_out, int out_size)
{
    const float* h   = (const float*)d_in[0];
    const float* x   = (const float*)d_in[1];
    const int*   ei  = (const int*)  d_in[2];
    const float* ea  = (const float*)d_in[3];
    const float* We1 = (const float*)d_in[4];
    const float* be1 = (const float*)d_in[5];
    const float* We2 = (const float*)d_in[6];
    const float* be2 = (const float*)d_in[7];
    const float* Wn1 = (const float*)d_in[8];
    const float* bn1 = (const float*)d_in[9];
    const float* Wn2 = (const float*)d_in[10];
    const float* bn2 = (const float*)d_in[11];
    const float* Wc1 = (const float*)d_in[12];
    const float* bc1 = (const float*)d_in[13];
    const float* Wc2 = (const float*)d_in[14];

    const int N = in_sizes[0] / HIDN;
    const int E = in_sizes[2] / 2;

    float* hout = (float*)d_out;
    float* xout = hout + (size_t)N * HIDN;

    float* mi = nullptr;
    cudaGetSymbolAddress((void**)&mi, g_mi);

    cudaFuncSetAttribute(edge_mma,  cudaFuncAttributeMaxDynamicSharedMemorySize, SMEM_EDGE);
    cudaFuncSetAttribute(pnode_mma, cudaFuncAttributeMaxDynamicSharedMemorySize, SMEM_P);
    cudaFuncSetAttribute(node_mma,  cudaFuncAttributeMaxDynamicSharedMemorySize, SMEM_NODE);

    const int wItems = (NCW1 + 2 * NC2 + NCEA + NCN1 + NCN2) * 2048;
    prep_weights<<<(wItems + 255) / 256, 256>>>(We1, We2, Wc1, Wn1, Wn2);

    prep_data<<<4736, 256>>>(h, ea, x, mi, xout, N, E);

    dim3 pgrid((N + EM - 1) / EM, 2);
    pnode_mma<<<pgrid, ETH, SMEM_P>>>(N);

    edge_mma<<<(E + EM - 1) / EM, ETH, SMEM_EDGE>>>(x, ei, We1, be1, be2, bc1, Wc2,
                                                    mi, xout, E);
    prep_mi<<<(N * 128 + 255) / 256, 256>>>(mi, N);
    node_mma<<<(N + EM - 1) / EM, ETH, SMEM_NODE>>>(h, bn1, bn2, hout, N);
}